// round 10
// baseline (speedup 1.0000x reference)
#include <cuda_runtime.h>
#include <cstdint>

// Top-4 mean pooling: (512, 2048, 7, 7) fp32 -> 1,048,576 rows of 49 floats,
// out[row] = mean(top4(row)).
//
// R10 = R9 (TMA bulk-copy feeding) + fence.proxy.async.shared::cta after
// mbarrier init. mbarrier.init is a generic-proxy write; cp.async.bulk's
// complete_tx is async-proxy. Without the fence the TMA engine can see a
// stale barrier -> lost completion -> infinite try_wait spin (the likely
// cause of the R9 container timeout).
//
// Feeding: ONE cp.async.bulk (UBLKCP) per 25,088-B tile issued by thread 0,
// 4-stage smem ring, 4 mbarriers, single shared parity flipped per ring wrap.
// Compute (proven R8): 2 threads/row, sorted top-4 of each 25-slot half
// (odd's overlap slot masked to -inf), merged via shfl.xor(1) bitonic split.

#define ROW_LEN 49
#define TROWS 128
#define NTHREADS 256
#define TILE_FLOATS (TROWS * ROW_LEN)          // 6272
#define TILE_BYTES (TILE_FLOATS * 4)           // 25,088 (16B multiple)
#define STAGES 4
#define MBAR_AREA 64                           // 4 mbarriers, 16B apart
#define SMEM_BYTES (MBAR_AREA + STAGES * TILE_BYTES)
#define NBLOCKS 296                            // 148 SMs * 2 blocks

__device__ __forceinline__ uint32_t smem_u32(const void* p) {
    return (uint32_t)__cvta_generic_to_shared(p);
}
__device__ __forceinline__ void mbar_init(uint32_t mbar, uint32_t count) {
    asm volatile("mbarrier.init.shared.b64 [%0], %1;" :: "r"(mbar), "r"(count) : "memory");
}
__device__ __forceinline__ void mbar_expect_tx(uint32_t mbar, uint32_t bytes) {
    asm volatile("mbarrier.arrive.expect_tx.shared.b64 _, [%0], %1;"
                 :: "r"(mbar), "r"(bytes) : "memory");
}
__device__ __forceinline__ void bulk_g2s(uint32_t dst, const void* gsrc,
                                         uint32_t bytes, uint32_t mbar) {
    asm volatile(
        "cp.async.bulk.shared::cta.global.mbarrier::complete_tx::bytes [%0], [%1], %2, [%3];"
        :: "r"(dst), "l"(gsrc), "r"(bytes), "r"(mbar) : "memory");
}
__device__ __forceinline__ void mbar_wait(uint32_t mbar, uint32_t parity) {
    uint32_t done;
    asm volatile(
        "{\n\t.reg .pred p;\n\t"
        "mbarrier.try_wait.parity.acquire.cta.shared::cta.b64 p, [%1], %2;\n\t"
        "selp.b32 %0, 1, 0, p;\n\t}"
        : "=r"(done) : "r"(mbar), "r"(parity) : "memory");
    if (!done) {
        asm volatile(
            "{\n\t.reg .pred P1;\n\t"
            "WL_%=:\n\t"
            "mbarrier.try_wait.parity.acquire.cta.shared::cta.b64 P1, [%0], %1, 0x989680;\n\t"
            "@P1 bra.uni WD_%=;\n\t"
            "bra.uni WL_%=;\n\t"
            "WD_%=:\n\t}"
            :: "r"(mbar), "r"(parity) : "memory");
    }
}

__global__ __launch_bounds__(NTHREADS)
void apool_topk4_tma(const float* __restrict__ in,
                     float* __restrict__ out,
                     int ntiles) {
    extern __shared__ char smem[];
    float* buf = reinterpret_cast<float*>(smem + MBAR_AREA);
    const uint32_t mbar0 = smem_u32(smem);          // mbar[s] at mbar0 + 16*s
    const uint32_t buf0 = smem_u32(buf);

    const int tid = threadIdx.x;
    const int stride = gridDim.x;
    const int myrow = tid >> 1;
    const int odd = tid & 1;
    const float NEG_INF = __int_as_float(0xff800000);

    if (tid == 0) {
        #pragma unroll
        for (int s = 0; s < STAGES; s++) mbar_init(mbar0 + 16 * s, 1);
        // Make the generic-proxy mbarrier init visible to the async proxy
        // BEFORE any cp.async.bulk targets these barriers (required; lost
        // complete_tx otherwise -> infinite wait).
        asm volatile("fence.proxy.async.shared::cta;" ::: "memory");
    }
    __syncthreads();

    int t = blockIdx.x;
    if (tid == 0) {
        #pragma unroll
        for (int s = 0; s < STAGES; s++) {
            const int tl = t + s * stride;
            if (tl < ntiles) {
                mbar_expect_tx(mbar0 + 16 * s, TILE_BYTES);
                bulk_g2s(buf0 + s * TILE_BYTES,
                         in + (size_t)tl * TILE_FLOATS, TILE_BYTES,
                         mbar0 + 16 * s);
            }
        }
    }

    int stage = 0;
    uint32_t ph = 0;   // shared parity: stages consumed round-robin
    for (; t < ntiles; t += stride) {
        mbar_wait(mbar0 + 16 * stage, ph);        // acquire: TMA data visible

        const int row = t * TROWS + myrow;
        // even: idx 0..24 (base +0); odd: idx 24..48 (base +24), slot 0 masked.
        const float* r = &buf[stage * TILE_FLOATS + myrow * ROW_LEN + odd * 24];

        float a = odd ? NEG_INF : r[0];
        float b = r[1], c = r[2], d = r[3];
        float tt;
        #define CE(x, y) { tt = fmaxf(x, y); y = fminf(x, y); x = tt; }
        CE(a, b); CE(c, d); CE(a, c); CE(b, d); CE(b, c);
        #undef CE

        #pragma unroll
        for (int i = 4; i < 25; i++) {
            float v = r[i];
            float na = fmaxf(a, v); v = fminf(a, v); a = na;
            float nb = fmaxf(b, v); v = fminf(b, v); b = nb;
            float nc = fmaxf(c, v); v = fminf(c, v); c = nc;
            d = fmaxf(d, v);
        }

        float pa = __shfl_xor_sync(0xffffffffu, a, 1);
        float pb = __shfl_xor_sync(0xffffffffu, b, 1);
        float pc = __shfl_xor_sync(0xffffffffu, c, 1);
        float pd = __shfl_xor_sync(0xffffffffu, d, 1);
        float res = (fmaxf(a, pd) + fmaxf(b, pc) + fmaxf(c, pb) + fmaxf(d, pa)) * 0.25f;

        __syncthreads();                          // all threads done reading stage
        if (tid == 0) {
            const int tl = t + STAGES * stride;   // next tenant of this stage
            if (tl < ntiles) {
                mbar_expect_tx(mbar0 + 16 * stage, TILE_BYTES);
                bulk_g2s(buf0 + stage * TILE_BYTES,
                         in + (size_t)tl * TILE_FLOATS, TILE_BYTES,
                         mbar0 + 16 * stage);
            }
        }

        if (!odd) out[row] = res;                 // even lanes: consecutive rows

        if (++stage == STAGES) { stage = 0; ph ^= 1; }
    }
}

// Tail rows (nrows % TROWS != 0) — not hit for this shape; trivial direct path.
__global__ void apool_topk4_tail(const float* __restrict__ in,
                                 float* __restrict__ out,
                                 int row0, int nrows) {
    const int row = row0 + blockIdx.x * blockDim.x + threadIdx.x;
    if (row >= nrows) return;
    const float* r = in + (size_t)row * ROW_LEN;
    float a = r[0], b = r[1], c = r[2], d = r[3];
    float tt;
    #define CE(x, y) { tt = fmaxf(x, y); y = fminf(x, y); x = tt; }
    CE(a, b); CE(c, d); CE(a, c); CE(b, d); CE(b, c);
    #undef CE
    for (int i = 4; i < ROW_LEN; i++) {
        float v = r[i];
        float na = fmaxf(a, v); v = fminf(a, v); a = na;
        float nb = fmaxf(b, v); v = fminf(b, v); b = nb;
        float nc = fmaxf(c, v); v = fminf(c, v); c = nc;
        d = fmaxf(d, v);
    }
    out[row] = (a + b + c + d) * 0.25f;
}

extern "C" void kernel_launch(void* const* d_in, const int* in_sizes, int n_in,
                              void* d_out, int out_size) {
    const float* in = (const float*)d_in[0];
    float* out = (float*)d_out;
    const int nrows = in_sizes[0] / ROW_LEN;     // 1,048,576
    const int ntiles = nrows / TROWS;            // 8192 full tiles
    const int rem = nrows - ntiles * TROWS;      // 0 for this shape

    static bool attr_set = false;
    if (!attr_set) {
        cudaFuncSetAttribute(apool_topk4_tma,
                             cudaFuncAttributeMaxDynamicSharedMemorySize,
                             SMEM_BYTES);
        attr_set = true;
    }
    const int grid = (ntiles < NBLOCKS) ? ntiles : NBLOCKS;
    if (ntiles > 0)
        apool_topk4_tma<<<grid, NTHREADS, SMEM_BYTES>>>(in, out, ntiles);
    if (rem > 0)
        apool_topk4_tail<<<(rem + 127) / 128, 128>>>(in, out,
                                                     ntiles * TROWS, nrows);
}